// round 9
// baseline (speedup 1.0000x reference)
#include <cuda_runtime.h>
#include <cuda_bf16.h>
#include <math.h>

#define BB   128
#define DD   20000
#define DM1  19999
#define HID  128
#define ST   20480     // padded bf16 row stride = 40*512
#define JC2  512
#define NBLK2 40
#define LDA  72        // bf16 smem row stride (144B)
#define NCH  8
#define CH   2500
#define LOG2PI 1.8378770664093453

// ---------------- device scratch (zero-init; consume-and-clear) ----------------
__device__ float  d_dlt[(size_t)BB * (DD + 1)];
__device__ __nv_bfloat16 d_hxb[(size_t)BB * ST];
__device__ __nv_bfloat16 d_encb[(size_t)HID * ST];
__device__ __nv_bfloat16 d_etab[(size_t)BB * ST];
__device__ __nv_bfloat16 d_dect[(size_t)HID * ST];
__device__ float  d_z[BB * HID];
__device__ float  d_g[BB * HID];
__device__ float  d_WtW[HID * HID];
__device__ float  d_u[BB * HID];
__device__ int    d_lo[DM1], d_mid[DM1], d_hi[DM1];
__device__ float  d_av[DM1], d_bv[DM1];
__device__ float  d_csum[BB * NCH];
__device__ float  d_sexp[BB];          // atomic Σexp per b
__device__ double d_sumx[BB], d_sumlg[BB], d_sxl[BB];
__device__ float  d_eta2[BB];
__device__ float  d_zg[BB], d_zWz[BB], d_z2[BB];

// ---------------- meta ----------------
__device__ __forceinline__ int lower_bound_i(const int* a, int n, int key) {
    int lo = 0, hi = n;
    while (lo < hi) { int m = (lo + hi) >> 1; if (a[m] < key) lo = m + 1; else hi = m; }
    return lo;
}

__global__ void k_meta(const int* __restrict__ rows, const int* __restrict__ cols,
                       const float* __restrict__ vals, int nnz) {
    int r = blockIdx.x * blockDim.x + threadIdx.x;
    if (r >= DM1) return;
    int s = lower_bound_i(rows, nnz, r);
    int e = lower_bound_i(rows, nnz, r + 1);
    d_lo[r] = cols[s];
    d_hi[r] = cols[e - 1] + 1;
    d_av[r] = vals[s];
    d_bv[r] = vals[e - 1];
    int a = s, b = e;
    while (a < b) { int m = (a + b) >> 1; if (vals[m] < 0.f) b = m; else a = m + 1; }
    d_mid[r] = cols[a];
}

// -------- dual scan (log(x+1) fp64-carry, x exact fp32) + hx emit + (Psi x)·eta --------
__global__ __launch_bounds__(512) void k_scan_hx(const float* __restrict__ x,
                                                 const float* __restrict__ eta) {
    int b = blockIdx.x, t = threadIdx.x, lane = t & 31, wid = t >> 5;
    extern __shared__ float2 PX[];           // DD+1 entries: (scan_log, scan_x)
    __shared__ double wtotd[16], woffd[16];
    __shared__ float  wtotf[16], wofff[16];
    __shared__ double s_lx[32];
    __shared__ float  s_lg[32];
    __shared__ float  redf[16];
    if (t < 32) {
        s_lx[t] = log((double)t + 1.0);
        s_lg[t] = (float)lgamma((double)t + 1.0);
    }
    __syncthreads();
    const float* xb = x + (size_t)b * DD;
    double carryl = 0.0; float carryx = 0.f;
    float sx = 0.f, slg = 0.f;
    if (t == 0) PX[0] = make_float2(0.f, 0.f);

    for (int base = 0; base < DD; base += 4096) {
        double locl[8]; float locx[8];
        double runl = 0.0; float runx = 0.f;
        int i0 = base + t * 8;
        #pragma unroll
        for (int v = 0; v < 8; v++) {
            int i = i0 + v;
            if (i < DD) {
                float xv = xb[i];
                int xi = (int)xv;
                double lv; float lg;
                if (xi >= 0 && xi < 32 && (float)xi == xv) { lv = s_lx[xi]; lg = s_lg[xi]; }
                else { lv = (double)logf(xv + 1.f); lg = lgammaf(xv + 1.f); }
                sx += xv; slg += lg; runl += lv; runx += xv;
            }
            locl[v] = runl; locx[v] = runx;
        }
        double vl = runl; float vx = runx;
        #pragma unroll
        for (int off = 1; off < 32; off <<= 1) {
            double nl = __shfl_up_sync(0xffffffffu, vl, off);
            float  nx = __shfl_up_sync(0xffffffffu, vx, off);
            if (lane >= off) { vl += nl; vx += nx; }
        }
        if (lane == 31) { wtotd[wid] = vl; wtotf[wid] = vx; }
        __syncthreads();
        if (wid == 0) {
            double wl = (lane < 16) ? wtotd[lane] : 0.0;
            float  wx = (lane < 16) ? wtotf[lane] : 0.f;
            #pragma unroll
            for (int off = 1; off < 16; off <<= 1) {
                double nl = __shfl_up_sync(0xffffffffu, wl, off);
                float  nx = __shfl_up_sync(0xffffffffu, wx, off);
                if (lane >= off) { wl += nl; wx += nx; }
            }
            if (lane < 16) { woffd[lane] = wl; wofff[lane] = wx; }
        }
        __syncthreads();
        double basl = carryl + (wid > 0 ? woffd[wid - 1] : 0.0) + (vl - runl);
        float  basx = carryx + (wid > 0 ? wofff[wid - 1] : 0.f) + (vx - runx);
        #pragma unroll
        for (int u = 0; u < 8; u++) {
            int i = i0 + u;
            if (i < DD) PX[i + 1] = make_float2((float)(basl + locl[u]), basx + locx[u]);
        }
        carryl += woffd[15]; carryx += wofff[15];
        __syncthreads();
    }

    // hx emit (bf16) + s2 = (Psi x)·eta
    __nv_bfloat16* hb = d_hxb + (size_t)b * ST;
    const float* eb = eta + (size_t)b * DM1;
    float s2 = 0.f;
    for (int j = t; j < ST; j += 512) {
        float hv = 0.f;
        if (j < DM1) {
            float2 pl = PX[d_lo[j]], pm = PX[d_mid[j]], ph = PX[d_hi[j]];
            float a = d_av[j], bb = d_bv[j];
            hv = a * (pm.x - pl.x) + bb * (ph.x - pm.x);
            s2 = fmaf(eb[j], a * (pm.y - pl.y) + bb * (ph.y - pm.y), s2);
        }
        hb[j] = __float2bfloat16(hv);
    }
    // reduce sx, slg, s2
    float vals3[3] = {sx, slg, s2};
    double* dsts[3] = {&d_sumx[b], &d_sumlg[b], &d_sxl[b]};
    #pragma unroll
    for (int q = 0; q < 3; q++) {
        float s = vals3[q];
        #pragma unroll
        for (int off = 16; off; off >>= 1) s += __shfl_down_sync(0xffffffffu, s, off);
        if (lane == 0) redf[wid] = s;
        __syncthreads();
        if (t == 0) { double a = 0.0; for (int i = 0; i < 16; i++) a += (double)redf[i]; *dsts[q] = a; }
        __syncthreads();
    }
}

// -------- etab: eta -> bf16 padded + eta^2 (no meta dep; runs at t=0) --------
__global__ __launch_bounds__(256) void k_etab(const float* __restrict__ eta) {
    int b = blockIdx.y;
    int j0 = 8 * (blockIdx.x * 256 + threadIdx.x);
    const float* eb = eta + (size_t)b * DM1;
    float e[8]; float s = 0.f;
    #pragma unroll
    for (int v = 0; v < 8; v++) {
        int j = j0 + v;
        float ev = (j < DM1) ? eb[j] : 0.f;
        e[v] = ev;
        s = fmaf(ev, ev, s);
    }
    unsigned pk[4];
    #pragma unroll
    for (int v = 0; v < 4; v++) {
        __nv_bfloat162 p = __floats2bfloat162_rn(e[2 * v], e[2 * v + 1]);
        pk[v] = *(unsigned*)&p;
    }
    *(uint4*)&d_etab[(size_t)b * ST + j0] = *(uint4*)pk;
    #pragma unroll
    for (int off = 16; off; off >>= 1) s += __shfl_down_sync(0xffffffffu, s, off);
    if ((threadIdx.x & 31) == 0) atomicAdd(&d_eta2[b], s);
}

// -------- scatter: difference-array REDs + per-chunk csum --------
__global__ __launch_bounds__(256) void k_scatter(const float* __restrict__ eta) {
    int b = blockIdx.y;
    int j0 = 8 * (blockIdx.x * 256 + threadIdx.x);
    __shared__ float scs[NCH];
    if (threadIdx.x < NCH) scs[threadIdx.x] = 0.f;
    __syncthreads();
    float* dp = d_dlt + (size_t)b * (DD + 1);
    const float* eb = eta + (size_t)b * DM1;
    float cl[NCH];
    #pragma unroll
    for (int q = 0; q < NCH; q++) cl[q] = 0.f;
    #pragma unroll
    for (int v = 0; v < 8; v++) {
        int j = j0 + v;
        if (j < DM1) {
            float ev = eb[j];
            float a = d_av[j], bb = d_bv[j];
            int il = d_lo[j], im = d_mid[j], ih = d_hi[j];
            float c0 = a * ev, c1 = (bb - a) * ev, c2 = -bb * ev;
            atomicAdd(dp + il, c0);
            atomicAdd(dp + im, c1);
            atomicAdd(dp + ih, c2);
            cl[min(il / CH, NCH - 1)] += c0;
            cl[min(im / CH, NCH - 1)] += c1;
            cl[min(ih / CH, NCH - 1)] += c2;
        }
    }
    #pragma unroll
    for (int q = 0; q < NCH; q++) {
        float cv = cl[q];
        #pragma unroll
        for (int off = 16; off; off >>= 1) cv += __shfl_down_sync(0xffffffffu, cv, off);
        if ((threadIdx.x & 31) == 0 && cv != 0.f) atomicAdd(&scs[q], cv);
    }
    __syncthreads();
    if (threadIdx.x < NCH) {
        float cv = scs[threadIdx.x];
        if (cv != 0.f) atomicAdd(&d_csum[b * NCH + threadIdx.x], cv);
    }
}

// ---------------- enc fp32 -> padded bf16 ----------------
__global__ __launch_bounds__(256) void k_cvt(const float* __restrict__ src,
                                             __nv_bfloat16* __restrict__ dst) {
    int r = blockIdx.y;
    int j0 = 8 * (blockIdx.x * 256 + threadIdx.x);
    if (j0 >= ST) return;
    const float* sb = src + (size_t)r * DM1;
    unsigned pk[4];
    #pragma unroll
    for (int v = 0; v < 4; v++) {
        int j = j0 + 2 * v;
        float f1 = (j < DM1)     ? sb[j]     : 0.f;
        float f2 = (j + 1 < DM1) ? sb[j + 1] : 0.f;
        __nv_bfloat162 p = __floats2bfloat162_rn(f1, f2);
        pk[v] = *(unsigned*)&p;
    }
    *(uint4*)&dst[(size_t)r * ST + j0] = *(uint4*)pk;
}

// ---------------- dec [j][128] fp32 -> dect [n][ST] bf16 ----------------
__global__ __launch_bounds__(256) void k_trans_dec(const float* __restrict__ dw) {
    __shared__ __nv_bfloat16 tile[64][132];
    int j0 = blockIdx.x * 64;
    int t = threadIdx.x;
    #pragma unroll
    for (int p = 0; p < 16; p++) {
        int idx = t + 256 * p;
        int jj = idx >> 6, c2 = idx & 63;
        int j = j0 + jj;
        float2 v = make_float2(0.f, 0.f);
        if (j < DM1) v = *(const float2*)(dw + (size_t)j * HID + 2 * c2);
        tile[jj][2 * c2]     = __float2bfloat16(v.x);
        tile[jj][2 * c2 + 1] = __float2bfloat16(v.y);
    }
    __syncthreads();
    #pragma unroll
    for (int p = 0; p < 16; p++) {
        int idx = t + 256 * p;
        int n = idx >> 5, jw = idx & 31;
        __nv_bfloat162 pk;
        pk.x = tile[2 * jw][n];
        pk.y = tile[2 * jw + 1][n];
        *(unsigned*)&d_dect[(size_t)n * ST + j0 + 2 * jw] = *(unsigned*)&pk;
    }
}

// ---------------- mma helper ----------------
__device__ __forceinline__ void mma_bf16(float* c, unsigned a0, unsigned a1, unsigned a2,
                                         unsigned a3, unsigned b0, unsigned b1) {
    asm volatile("mma.sync.aligned.m16n8k16.row.col.f32.bf16.bf16.f32 "
                 "{%0,%1,%2,%3}, {%4,%5,%6,%7}, {%8,%9}, {%0,%1,%2,%3};\n"
                 : "+f"(c[0]), "+f"(c[1]), "+f"(c[2]), "+f"(c[3])
                 : "r"(a0), "r"(a1), "r"(a2), "r"(a3), "r"(b0), "r"(b1));
}

// ---------------- combined GEMM: y=0 z, y=1 g, y=2 WtW ----------------
__global__ __launch_bounds__(256, 2) void k_gemm_all() {
    __shared__ __nv_bfloat16 As[128 * LDA], Bs[128 * LDA];
    const __nv_bfloat16 *A, *B; float* C;
    if (blockIdx.y == 0)      { A = d_hxb;  B = d_encb; C = d_z; }
    else if (blockIdx.y == 1) { A = d_etab; B = d_dect; C = d_g; }
    else                      { A = d_dect; B = d_dect; C = d_WtW; }
    int j0 = blockIdx.x * JC2;
    int t = threadIdx.x, lane = t & 31, w = t >> 5;
    int wm = w & 1, wn = w >> 1;
    int lr = t >> 3, lc = (t & 7) * 8;
    float acc[4][4][4];
    #pragma unroll
    for (int a = 0; a < 4; a++)
        #pragma unroll
        for (int b = 0; b < 4; b++)
            #pragma unroll
            for (int c = 0; c < 4; c++) acc[a][b][c] = 0.f;

    #pragma unroll
    for (int ch = 0; ch < 8; ch++) {
        int js = j0 + 64 * ch;
        #pragma unroll
        for (int p = 0; p < 4; p++) {
            int row = lr + 32 * p;
            *(uint4*)&As[row * LDA + lc] = *(const uint4*)(A + (size_t)row * ST + js + lc);
            *(uint4*)&Bs[row * LDA + lc] = *(const uint4*)(B + (size_t)row * ST + js + lc);
        }
        __syncthreads();
        #pragma unroll
        for (int kk = 0; kk < 4; kk++) {
            int co = kk * 16 + 2 * (lane & 3);
            unsigned a[4][4], b[4][2];
            #pragma unroll
            for (int mt = 0; mt < 4; mt++) {
                int r = wm * 64 + mt * 16 + (lane >> 2);
                a[mt][0] = *(const unsigned*)&As[r * LDA + co];
                a[mt][1] = *(const unsigned*)&As[(r + 8) * LDA + co];
                a[mt][2] = *(const unsigned*)&As[r * LDA + co + 8];
                a[mt][3] = *(const unsigned*)&As[(r + 8) * LDA + co + 8];
            }
            #pragma unroll
            for (int nt = 0; nt < 4; nt++) {
                int n = wn * 32 + nt * 8 + (lane >> 2);
                b[nt][0] = *(const unsigned*)&Bs[n * LDA + co];
                b[nt][1] = *(const unsigned*)&Bs[n * LDA + co + 8];
            }
            #pragma unroll
            for (int mt = 0; mt < 4; mt++)
                #pragma unroll
                for (int nt = 0; nt < 4; nt++)
                    mma_bf16(acc[mt][nt], a[mt][0], a[mt][1], a[mt][2], a[mt][3],
                             b[nt][0], b[nt][1]);
        }
        __syncthreads();
    }
    #pragma unroll
    for (int mt = 0; mt < 4; mt++)
        #pragma unroll
        for (int nt = 0; nt < 4; nt++) {
            int r = wm * 64 + mt * 16 + (lane >> 2);
            int c = wn * 32 + nt * 8 + 2 * (lane & 3);
            atomicAdd(&C[r * HID + c],           acc[mt][nt][0]);
            atomicAdd(&C[r * HID + c + 1],       acc[mt][nt][1]);
            atomicAdd(&C[(r + 8) * HID + c],     acc[mt][nt][2]);
            atomicAdd(&C[(r + 8) * HID + c + 1], acc[mt][nt][3]);
        }
}

// -------- mult: per-chunk scan of dlt + Σexp only (clears dlt) --------
__global__ __launch_bounds__(512) void k_mult_b() {
    int c = blockIdx.x, b = blockIdx.y, t = threadIdx.x, lane = t & 31, wid = t >> 5;
    int off0 = c * CH;
    float* dp = d_dlt + (size_t)b * (DD + 1) + off0;
    __shared__ float wtot[16], woff[16], redf[16];

    float carry = 0.f;
    {
        const float* cs = d_csum + b * NCH;
        #pragma unroll
        for (int q = 0; q < NCH; q++) if (q < c) carry += cs[q];
    }
    if (c == NCH - 1 && t == 0) d_dlt[(size_t)b * (DD + 1) + DD] = 0.f;

    float sexp = 0.f;
    {
        float loc[8]; float run = 0.f;
        int i0 = t * 8;
        #pragma unroll
        for (int v = 0; v < 8; v++) {
            int i = i0 + v;
            float dv = 0.f;
            if (i < CH) { dv = dp[i]; dp[i] = 0.f; }
            run += dv;
            loc[v] = run;
        }
        float v = run;
        #pragma unroll
        for (int off = 1; off < 32; off <<= 1) {
            float nv = __shfl_up_sync(0xffffffffu, v, off);
            if (lane >= off) v += nv;
        }
        if (lane == 31) wtot[wid] = v;
        __syncthreads();
        if (wid == 0) {
            float w = (lane < 16) ? wtot[lane] : 0.f;
            #pragma unroll
            for (int off = 1; off < 16; off <<= 1) {
                float nv = __shfl_up_sync(0xffffffffu, w, off);
                if (lane >= off) w += nv;
            }
            if (lane < 16) woff[lane] = w;
        }
        __syncthreads();
        float basf = carry + (wid > 0 ? woff[wid - 1] : 0.f) + (v - run);
        #pragma unroll
        for (int u = 0; u < 8; u++) {
            int i = i0 + u;
            if (i < CH) sexp += expf(basf + loc[u]);
        }
    }
    #pragma unroll
    for (int off = 16; off; off >>= 1) sexp += __shfl_down_sync(0xffffffffu, sexp, off);
    if (lane == 0) redf[wid] = sexp;
    __syncthreads();
    if (t == 0) {
        float a = 0.f;
        for (int i = 0; i < 16; i++) a += redf[i];
        atomicAdd(&d_sexp[b], a);
    }
}

// ---------------- u = (g - z@WtW)*sD, quad pieces (clears z, g) ----------------
__global__ void k_uquad(const float* __restrict__ vlv) {
    int b = blockIdx.x, k = threadIdx.x;
    __shared__ float zs[128];
    __shared__ float rd[128];
    zs[k] = d_z[b * HID + k];
    d_z[b * HID + k] = 0.f;
    __syncthreads();
    float wv = 0.f;
    #pragma unroll 8
    for (int k2 = 0; k2 < 128; k2++) wv = fmaf(zs[k2], d_WtW[k2 * HID + k], wv);
    float g = d_g[b * HID + k];
    d_g[b * HID + k] = 0.f;
    float sd = expf(0.5f * vlv[k]);
    d_u[b * HID + k] = (g - wv) * sd;
    float z = zs[k];

    rd[k] = z * g; __syncthreads();
    for (int off = 64; off; off >>= 1) { if (k < off) rd[k] += rd[k + off]; __syncthreads(); }
    if (k == 0) d_zg[b] = rd[0];
    __syncthreads();
    rd[k] = z * wv; __syncthreads();
    for (int off = 64; off; off >>= 1) { if (k < off) rd[k] += rd[k + off]; __syncthreads(); }
    if (k == 0) d_zWz[b] = rd[0];
    __syncthreads();
    rd[k] = z * z; __syncthreads();
    for (int off = 64; off; off >>= 1) { if (k < off) rd[k] += rd[k + off]; __syncthreads(); }
    if (k == 0) d_z2[b] = rd[0];
}

// ---------------- final: Cholesky + solve + loss (clears WtW, eta2, sexp, csum) ----------------
__global__ __launch_bounds__(512) void k_final(const float* __restrict__ vlv,
                                               const float* __restrict__ lss_ptr,
                                               float* __restrict__ out) {
    extern __shared__ float smf[];
    float* Mm = smf;
    float* R  = smf + 128 * 129;
    __shared__ __align__(16) float Lp[120 * 8];
    __shared__ float sinv[8];
    __shared__ float sD[128];
    __shared__ double s_ld;
    __shared__ double red[512];
    int t = threadIdx.x, lane = t & 31;
    float lss = *lss_ptr;
    float var = expf(lss);
    float ivar = 1.f / var;
    if (t < 128) sD[t] = expf(0.5f * vlv[t]);
    d_csum[t] = 0.f;
    d_csum[512 + t] = 0.f;
    __syncthreads();
    for (int idx = t; idx < 128 * 128; idx += 512) {
        int i = idx >> 7, j = idx & 127;
        float wv = d_WtW[idx];
        d_WtW[idx] = 0.f;
        float m = sD[i] * wv * sD[j] * ivar;
        if (i == j) m += 1.f;
        Mm[i * 129 + j] = m;
    }
    for (int idx = t; idx < 128 * 128; idx += 512) {
        int b = idx >> 7, i = idx & 127;
        R[i * 129 + b] = d_u[idx];
    }
    __syncthreads();

    float qacc = 0.f;
    double ldacc = 0.0;

    for (int p = 0; p < 16; p++) {
        int k0 = 8 * p;
        if (t < 32) {
            int r = lane & 7;
            float v[8];
            #pragma unroll
            for (int c = 0; c < 8; c++) v[c] = Mm[(k0 + r) * 129 + k0 + c];
            #pragma unroll
            for (int kk = 0; kk < 8; kk++) {
                float dkk = __shfl_sync(0xffffffffu, v[kk], kk);
                float d = sqrtf(dkk);
                float inv = 1.f / d;
                if (lane == kk) { v[kk] = d; ldacc += 2.0 * log((double)d); }
                if (r > kk && lane != kk) v[kk] *= inv;
                #pragma unroll
                for (int c = kk + 1; c < 8; c++) {
                    float Lck = __shfl_sync(0xffffffffu, v[kk], c);
                    if (r > kk) v[c] -= v[kk] * Lck;
                }
            }
            if (lane < 8) {
                #pragma unroll
                for (int c = 0; c < 8; c++) Mm[(k0 + r) * 129 + k0 + c] = v[c];
                sinv[r] = 1.f / v[r];
            }
        }
        __syncthreads();

        int nrem = 120 - k0;
        if (t < nrem) {
            int i = k0 + 8 + t;
            float a[8];
            #pragma unroll
            for (int c = 0; c < 8; c++) a[c] = Mm[i * 129 + k0 + c];
            #pragma unroll
            for (int c = 0; c < 8; c++) {
                float s = a[c];
                #pragma unroll
                for (int q = 0; q < 8; q++) if (q < c) s -= a[q] * Mm[(k0 + c) * 129 + k0 + q];
                a[c] = s * sinv[c];
            }
            #pragma unroll
            for (int c = 0; c < 8; c++) { Mm[i * 129 + k0 + c] = a[c]; Lp[t * 8 + c] = a[c]; }
        } else if (t >= 256 && t < 384) {
            int b = t - 256;
            float y[8];
            #pragma unroll
            for (int c = 0; c < 8; c++) y[c] = R[(k0 + c) * 129 + b];
            #pragma unroll
            for (int c = 0; c < 8; c++) {
                float s = y[c];
                #pragma unroll
                for (int q = 0; q < 8; q++) if (q < c) s -= y[q] * Mm[(k0 + c) * 129 + k0 + q];
                y[c] = s * sinv[c];
                qacc = fmaf(y[c], y[c], qacc);
            }
            #pragma unroll
            for (int c = 0; c < 8; c++) R[(k0 + c) * 129 + b] = y[c];
        }
        __syncthreads();

        int base = k0 + 8, n = 128 - base;
        if (n > 0) {
            int io = t & 127, jg = t >> 7;
            if (io < n) {
                int i = base + io;
                float Li[8];
                #pragma unroll
                for (int q = 0; q < 8; q++) Li[q] = Lp[io * 8 + q];
                for (int jo = jg; jo < n; jo += 4) {
                    int j = base + jo;
                    const float4* lp4 = (const float4*)&Lp[jo * 8];
                    float4 L0 = lp4[0], L1 = lp4[1];
                    float s = Mm[i * 129 + j];
                    s -= Li[0] * L0.x + Li[1] * L0.y + Li[2] * L0.z + Li[3] * L0.w
                       + Li[4] * L1.x + Li[5] * L1.y + Li[6] * L1.z + Li[7] * L1.w;
                    Mm[i * 129 + j] = s;
                }
            }
            {
                int b = t & 127, ig = t >> 7;
                float y[8];
                #pragma unroll
                for (int q = 0; q < 8; q++) y[q] = R[(k0 + q) * 129 + b];
                for (int io2 = ig; io2 < n; io2 += 4) {
                    int i = base + io2;
                    const float4* lp4 = (const float4*)&Lp[io2 * 8];
                    float4 L0 = lp4[0], L1 = lp4[1];
                    float s = R[i * 129 + b];
                    s -= y[0] * L0.x + y[1] * L0.y + y[2] * L0.z + y[3] * L0.w
                       + y[4] * L1.x + y[5] * L1.y + y[6] * L1.z + y[7] * L1.w;
                    R[i * 129 + b] = s;
                }
            }
        }
        __syncthreads();
    }

    if (t < 32) {
        #pragma unroll
        for (int off = 16; off; off >>= 1) ldacc += __shfl_down_sync(0xffffffffu, ldacc, off);
        if (lane == 0) s_ld = ldacc;
    }
    __syncthreads();

    double acc = 0.0;
    if (t >= 256 && t < 384) {
        int b = t - 256;
        float sexp = d_sexp[b];
        d_sexp[b] = 0.f;
        double sx = d_sumx[b];
        double multb = lgamma(sx + 1.0) - d_sumlg[b] + d_sxl[b] - sx * log((double)sexp);
        float e2 = d_eta2[b];
        d_eta2[b] = 0.f;
        float quad = (e2 - 2.f * d_zg[b] + d_zWz[b]) * ivar - qacc * ivar * ivar;
        double logdet = (double)DM1 * (double)lss + s_ld;
        double ll = -0.5 * ((double)DM1 * LOG2PI + logdet + (double)quad);
        acc = ll + multb - 0.5 * (double)d_z2[b] / 128.0;
    }
    red[t] = acc;
    __syncthreads();
    for (int off = 256; off; off >>= 1) { if (t < off) red[t] += red[t + off]; __syncthreads(); }
    if (t == 0) {
        double total = red[0] / 128.0 - 0.5 * LOG2PI;
        out[0] = (float)(-total);
    }
}

// ---------------- launcher ----------------
static cudaStream_t s2, s3, s4;
static cudaEvent_t ev_root, ev_meta, ev_s3, ev_etab, ev_mult;
static bool g_init = false;

extern "C" void kernel_launch(void* const* d_in, const int* in_sizes, int n_in,
                              void* d_out, int out_size) {
    const float* x     = (const float*)d_in[0];
    const int*   rows  = (const int*)  d_in[1];
    const int*   cols  = (const int*)  d_in[2];
    const float* vals  = (const float*)d_in[3];
    const float* enc_w = (const float*)d_in[4];
    const float* dec_w = (const float*)d_in[5];
    const float* vlv   = (const float*)d_in[6];
    const float* lss   = (const float*)d_in[7];
    const float* eta   = (const float*)d_in[8];
    int nnz = in_sizes[1];
    float* out = (float*)d_out;

    if (!g_init) {
        cudaStreamCreateWithFlags(&s2, cudaStreamNonBlocking);
        cudaStreamCreateWithFlags(&s3, cudaStreamNonBlocking);
        cudaStreamCreateWithFlags(&s4, cudaStreamNonBlocking);
        cudaEventCreateWithFlags(&ev_root, cudaEventDisableTiming);
        cudaEventCreateWithFlags(&ev_meta, cudaEventDisableTiming);
        cudaEventCreateWithFlags(&ev_s3,   cudaEventDisableTiming);
        cudaEventCreateWithFlags(&ev_etab, cudaEventDisableTiming);
        cudaEventCreateWithFlags(&ev_mult, cudaEventDisableTiming);
        cudaFuncSetAttribute(k_final, cudaFuncAttributeMaxDynamicSharedMemorySize,
                             2 * 128 * 129 * (int)sizeof(float));
        cudaFuncSetAttribute(k_scan_hx, cudaFuncAttributeMaxDynamicSharedMemorySize,
                             (DD + 1) * (int)sizeof(float2));
        g_init = true;
    }

    cudaEventRecord(ev_root, 0);
    cudaStreamWaitEvent(s2, ev_root, 0);
    cudaStreamWaitEvent(s3, ev_root, 0);
    cudaStreamWaitEvent(s4, ev_root, 0);

    // s0: meta -> scan_hx -> [s3, etab] gemm_all -> uquad -> [mult] final
    k_meta<<<(DM1 + 255) / 256, 256, 0, 0>>>(rows, cols, vals, nnz);
    cudaEventRecord(ev_meta, 0);
    k_scan_hx<<<BB, 512, (DD + 1) * sizeof(float2), 0>>>(x, eta);

    // s3: cvt_enc -> trans_dec (t=0)
    {
        dim3 gcv(ST / 8 / 256, HID);
        k_cvt<<<gcv, 256, 0, s3>>>(enc_w, d_encb);
    }
    k_trans_dec<<<ST / 64, 256, 0, s3>>>(dec_w);
    cudaEventRecord(ev_s3, s3);

    // s4: etab + eta^2 (t=0)
    {
        dim3 ge(ST / 8 / 256, BB);
        k_etab<<<ge, 256, 0, s4>>>(eta);
    }
    cudaEventRecord(ev_etab, s4);

    // s2: (meta) -> scatter -> mult_b
    cudaStreamWaitEvent(s2, ev_meta, 0);
    {
        dim3 gs(ST / 8 / 256, BB);
        k_scatter<<<gs, 256, 0, s2>>>(eta);
    }
    {
        dim3 gm(NCH, BB);
        k_mult_b<<<gm, 512, 0, s2>>>();
    }
    cudaEventRecord(ev_mult, s2);

    // s0 tail
    cudaStreamWaitEvent(0, ev_s3, 0);
    cudaStreamWaitEvent(0, ev_etab, 0);
    {
        dim3 gg(NBLK2, 3);
        k_gemm_all<<<gg, 256, 0, 0>>>();
    }
    k_uquad<<<BB, 128, 0, 0>>>(vlv);
    cudaStreamWaitEvent(0, ev_mult, 0);
    k_final<<<1, 512, 2 * 128 * 129 * sizeof(float), 0>>>(vlv, lss, out);
}

// round 10
// speedup vs baseline: 1.0589x; 1.0589x over previous
#include <cuda_runtime.h>
#include <cuda_bf16.h>
#include <math.h>

#define BB   128
#define DD   20000
#define DM1  19999
#define HID  128
#define ST   20224     // padded bf16 row stride = 79*256
#define JC2  256
#define NBLK2 79
#define LDA  72        // bf16 smem row stride (144B)
#define LOG2PI 1.8378770664093453

// ---------------- device scratch ----------------
__device__ float  d_dlt[(size_t)BB * (DD + 1)];
__device__ __nv_bfloat16 d_hxb[(size_t)BB * ST];
__device__ __nv_bfloat16 d_encb[(size_t)HID * ST];
__device__ __nv_bfloat16 d_etab[(size_t)BB * ST];
__device__ __nv_bfloat16 d_dect[(size_t)HID * ST];
__device__ float  d_z[BB * HID];
__device__ float  d_g[BB * HID];
__device__ float  d_WtW[HID * HID];
__device__ float  d_u[BB * HID];
__device__ int    d_lo[DM1], d_mid[DM1], d_hi[DM1];
__device__ float  d_av[DM1], d_bv[DM1];
__device__ double d_mult[BB];
__device__ float  d_eta2[BB];
__device__ float  d_zg[BB], d_zWz[BB], d_z2[BB];

// ---------------- meta ----------------
__device__ __forceinline__ int lower_bound_i(const int* a, int n, int key) {
    int lo = 0, hi = n;
    while (lo < hi) { int m = (lo + hi) >> 1; if (a[m] < key) lo = m + 1; else hi = m; }
    return lo;
}

__global__ void k_meta(const int* __restrict__ rows, const int* __restrict__ cols,
                       const float* __restrict__ vals, int nnz) {
    int r = blockIdx.x * blockDim.x + threadIdx.x;
    if (r >= DM1) return;
    int s = lower_bound_i(rows, nnz, r);
    int e = lower_bound_i(rows, nnz, r + 1);
    d_lo[r] = cols[s];
    d_hi[r] = cols[e - 1] + 1;
    d_av[r] = vals[s];
    d_bv[r] = vals[e - 1];
    int a = s, b = e;
    while (a < b) { int m = (a + b) >> 1; if (vals[m] < 0.f) b = m; else a = m + 1; }
    d_mid[r] = cols[a];
}

// ---------------- scan log(x+1) in smem, emit bf16 hx directly ----------------
__global__ __launch_bounds__(512) void k_scan_hx(const float* __restrict__ x) {
    int b = blockIdx.x, t = threadIdx.x, lane = t & 31, wid = t >> 5;
    extern __shared__ float P[];             // DD+1 floats
    __shared__ double wtot[16], woff[16];
    __shared__ double s_lx[32];
    if (t < 32) s_lx[t] = log((double)t + 1.0);
    __syncthreads();
    const float* xb = x + (size_t)b * DD;
    double carry = 0.0;
    if (t == 0) P[0] = 0.f;

    for (int base = 0; base < DD; base += 4096) {
        double loc[8]; double run = 0.0;
        int i0 = base + t * 8;
        #pragma unroll
        for (int v = 0; v < 8; v++) {
            int i = i0 + v;
            if (i < DD) {
                float xv = xb[i];
                int xi = (int)xv;
                double lv = (xi >= 0 && xi < 32 && (float)xi == xv)
                          ? s_lx[xi] : (double)logf(xv + 1.f);
                run += lv;
            }
            loc[v] = run;
        }
        double v = run;
        #pragma unroll
        for (int off = 1; off < 32; off <<= 1) {
            double nv = __shfl_up_sync(0xffffffffu, v, off);
            if (lane >= off) v += nv;
        }
        if (lane == 31) wtot[wid] = v;
        __syncthreads();
        if (wid == 0) {
            double w = (lane < 16) ? wtot[lane] : 0.0;
            #pragma unroll
            for (int off = 1; off < 16; off <<= 1) {
                double nv = __shfl_up_sync(0xffffffffu, w, off);
                if (lane >= off) w += nv;
            }
            if (lane < 16) woff[lane] = w;
        }
        __syncthreads();
        double basd = carry + (wid > 0 ? woff[wid - 1] : 0.0) + (v - run);
        #pragma unroll
        for (int u = 0; u < 8; u++) {
            int i = i0 + u;
            if (i < DD) P[i + 1] = (float)(basd + loc[u]);
        }
        carry += woff[15];
        __syncthreads();
    }

    __nv_bfloat16* hb = d_hxb + (size_t)b * ST;
    for (int j = t; j < ST; j += 512) {
        float hv = 0.f;
        if (j < DM1) {
            float pl = P[d_lo[j]], pm = P[d_mid[j]], ph = P[d_hi[j]];
            hv = d_av[j] * (pm - pl) + d_bv[j] * (ph - pm);
        }
        hb[j] = __float2bfloat16(hv);
    }
}

// ---------------- eta -> bf16 padded + global scatter + eta^2 ----------------
__global__ __launch_bounds__(256) void k_cvt_eta(const float* __restrict__ eta) {
    int b = blockIdx.y;
    int j0 = 8 * (blockIdx.x * 256 + threadIdx.x);
    float* dp = d_dlt + (size_t)b * (DD + 1);
    const float* eb = eta + (size_t)b * DM1;
    float e[8];
    float s = 0.f;
    #pragma unroll
    for (int v = 0; v < 8; v++) {
        int j = j0 + v;
        float ev = (j < DM1) ? eb[j] : 0.f;
        e[v] = ev;
        s = fmaf(ev, ev, s);
        if (j < DM1) {
            float a = d_av[j], bb = d_bv[j];
            atomicAdd(dp + d_lo[j],  a * ev);
            atomicAdd(dp + d_mid[j], (bb - a) * ev);
            atomicAdd(dp + d_hi[j], -bb * ev);
        }
    }
    if (j0 < ST) {
        unsigned pk[4];
        #pragma unroll
        for (int v = 0; v < 4; v++) {
            __nv_bfloat162 p = __floats2bfloat162_rn(e[2 * v], e[2 * v + 1]);
            pk[v] = *(unsigned*)&p;
        }
        *(uint4*)&d_etab[(size_t)b * ST + j0] = *(uint4*)pk;
    }
    #pragma unroll
    for (int off = 16; off; off >>= 1) s += __shfl_down_sync(0xffffffffu, s, off);
    if ((threadIdx.x & 31) == 0) atomicAdd(&d_eta2[b], s);
}

// ---------------- enc fp32 -> padded bf16 ----------------
__global__ __launch_bounds__(256) void k_cvt(const float* __restrict__ src,
                                             __nv_bfloat16* __restrict__ dst) {
    int r = blockIdx.y;
    int j0 = 8 * (blockIdx.x * 256 + threadIdx.x);
    if (j0 >= ST) return;
    const float* sb = src + (size_t)r * DM1;
    unsigned pk[4];
    #pragma unroll
    for (int v = 0; v < 4; v++) {
        int j = j0 + 2 * v;
        float f1 = (j < DM1)     ? sb[j]     : 0.f;
        float f2 = (j + 1 < DM1) ? sb[j + 1] : 0.f;
        __nv_bfloat162 p = __floats2bfloat162_rn(f1, f2);
        pk[v] = *(unsigned*)&p;
    }
    *(uint4*)&dst[(size_t)r * ST + j0] = *(uint4*)pk;
}

// ---------------- dec [j][128] fp32 -> dect [n][ST] bf16 ----------------
__global__ __launch_bounds__(256) void k_trans_dec(const float* __restrict__ dw) {
    __shared__ __nv_bfloat16 tile[64][132];
    int j0 = blockIdx.x * 64;
    int t = threadIdx.x;
    #pragma unroll
    for (int p = 0; p < 16; p++) {
        int idx = t + 256 * p;
        int jj = idx >> 6, c2 = idx & 63;
        int j = j0 + jj;
        float2 v = make_float2(0.f, 0.f);
        if (j < DM1) v = *(const float2*)(dw + (size_t)j * HID + 2 * c2);
        tile[jj][2 * c2]     = __float2bfloat16(v.x);
        tile[jj][2 * c2 + 1] = __float2bfloat16(v.y);
    }
    __syncthreads();
    #pragma unroll
    for (int p = 0; p < 16; p++) {
        int idx = t + 256 * p;
        int n = idx >> 5, jw = idx & 31;
        __nv_bfloat162 pk;
        pk.x = tile[2 * jw][n];
        pk.y = tile[2 * jw + 1][n];
        *(unsigned*)&d_dect[(size_t)n * ST + j0 + 2 * jw] = *(unsigned*)&pk;
    }
}

// ---------------- mma helper ----------------
__device__ __forceinline__ void mma_bf16(float* c, unsigned a0, unsigned a1, unsigned a2,
                                         unsigned a3, unsigned b0, unsigned b1) {
    asm volatile("mma.sync.aligned.m16n8k16.row.col.f32.bf16.bf16.f32 "
                 "{%0,%1,%2,%3}, {%4,%5,%6,%7}, {%8,%9}, {%0,%1,%2,%3};\n"
                 : "+f"(c[0]), "+f"(c[1]), "+f"(c[2]), "+f"(c[3])
                 : "r"(a0), "r"(a1), "r"(a2), "r"(a3), "r"(b0), "r"(b1));
}

__device__ __forceinline__ void mma_chunk(const __nv_bfloat16* As, const __nv_bfloat16* Bs,
                                          float acc[4][4][4], int lane, int wm, int wn) {
    #pragma unroll
    for (int kk = 0; kk < 4; kk++) {
        int co = kk * 16 + 2 * (lane & 3);
        unsigned a[4][4], b[4][2];
        #pragma unroll
        for (int mt = 0; mt < 4; mt++) {
            int r = wm * 64 + mt * 16 + (lane >> 2);
            a[mt][0] = *(const unsigned*)&As[r * LDA + co];
            a[mt][1] = *(const unsigned*)&As[(r + 8) * LDA + co];
            a[mt][2] = *(const unsigned*)&As[r * LDA + co + 8];
            a[mt][3] = *(const unsigned*)&As[(r + 8) * LDA + co + 8];
        }
        #pragma unroll
        for (int nt = 0; nt < 4; nt++) {
            int n = wn * 32 + nt * 8 + (lane >> 2);
            b[nt][0] = *(const unsigned*)&Bs[n * LDA + co];
            b[nt][1] = *(const unsigned*)&Bs[n * LDA + co + 8];
        }
        #pragma unroll
        for (int mt = 0; mt < 4; mt++)
            #pragma unroll
            for (int nt = 0; nt < 4; nt++)
                mma_bf16(acc[mt][nt], a[mt][0], a[mt][1], a[mt][2], a[mt][3],
                         b[nt][0], b[nt][1]);
    }
}

__device__ __forceinline__ void gemm_epi(float* C, float acc[4][4][4], int lane, int wm, int wn) {
    #pragma unroll
    for (int mt = 0; mt < 4; mt++)
        #pragma unroll
        for (int nt = 0; nt < 4; nt++) {
            int r = wm * 64 + mt * 16 + (lane >> 2);
            int c = wn * 32 + nt * 8 + 2 * (lane & 3);
            atomicAdd(&C[r * HID + c],           acc[mt][nt][0]);
            atomicAdd(&C[r * HID + c + 1],       acc[mt][nt][1]);
            atomicAdd(&C[(r + 8) * HID + c],     acc[mt][nt][2]);
            atomicAdd(&C[(r + 8) * HID + c + 1], acc[mt][nt][3]);
        }
}

__device__ __forceinline__ void gemm_nn(const __nv_bfloat16* __restrict__ A,
                                        const __nv_bfloat16* __restrict__ B,
                                        float* __restrict__ C,
                                        __nv_bfloat16* As, __nv_bfloat16* Bs) {
    int j0 = blockIdx.x * JC2;
    int t = threadIdx.x, lane = t & 31, w = t >> 5;
    int wm = w & 1, wn = w >> 1;
    int lr = t >> 3, lc = (t & 7) * 8;
    float acc[4][4][4];
    #pragma unroll
    for (int a = 0; a < 4; a++)
        #pragma unroll
        for (int b = 0; b < 4; b++)
            #pragma unroll
            for (int c = 0; c < 4; c++) acc[a][b][c] = 0.f;

    #pragma unroll
    for (int ch = 0; ch < 4; ch++) {
        int js = j0 + 64 * ch;
        #pragma unroll
        for (int p = 0; p < 4; p++) {
            int row = lr + 32 * p;
            *(uint4*)&As[row * LDA + lc] = *(const uint4*)(A + (size_t)row * ST + js + lc);
            *(uint4*)&Bs[row * LDA + lc] = *(const uint4*)(B + (size_t)row * ST + js + lc);
        }
        __syncthreads();
        mma_chunk(As, Bs, acc, lane, wm, wn);
        __syncthreads();
    }
    gemm_epi(C, acc, lane, wm, wn);
}

__global__ __launch_bounds__(256, 2) void k_gemm_z() {
    __shared__ __nv_bfloat16 As[128 * LDA], Bs[128 * LDA];
    gemm_nn(d_hxb, d_encb, d_z, As, Bs);
}
__global__ __launch_bounds__(256, 2) void k_gemm_g() {
    __shared__ __nv_bfloat16 As[128 * LDA], Bs[128 * LDA];
    gemm_nn(d_etab, d_dect, d_g, As, Bs);
}
__global__ __launch_bounds__(256, 2) void k_gemm_w() {
    __shared__ __nv_bfloat16 As[128 * LDA];
    int j0 = blockIdx.x * JC2;
    int t = threadIdx.x, lane = t & 31, w = t >> 5;
    int wm = w & 1, wn = w >> 1;
    int lr = t >> 3, lc = (t & 7) * 8;
    float acc[4][4][4];
    #pragma unroll
    for (int a = 0; a < 4; a++)
        #pragma unroll
        for (int b = 0; b < 4; b++)
            #pragma unroll
            for (int c = 0; c < 4; c++) acc[a][b][c] = 0.f;
    #pragma unroll
    for (int ch = 0; ch < 4; ch++) {
        int js = j0 + 64 * ch;
        #pragma unroll
        for (int p = 0; p < 4; p++) {
            int row = lr + 32 * p;
            *(uint4*)&As[row * LDA + lc] = *(const uint4*)(d_dect + (size_t)row * ST + js + lc);
        }
        __syncthreads();
        mma_chunk(As, As, acc, lane, wm, wn);
        __syncthreads();
    }
    gemm_epi(d_WtW, acc, lane, wm, wn);
}

// ---------------- logits scan + multinomial (reads global dlt) ----------------
__global__ __launch_bounds__(512) void k_mult(const float* __restrict__ x) {
    int b = blockIdx.x, t = threadIdx.x, lane = t & 31, wid = t >> 5;
    const float* xb = x + (size_t)b * DD;
    const float* db = d_dlt + (size_t)b * (DD + 1);
    __shared__ float wtot[16], woff[16], redf[16];
    __shared__ float s_lg[32];
    __shared__ double s_acc[4];
    if (t < 32) s_lg[t] = (float)lgamma((double)t + 1.0);
    __syncthreads();
    float carry = 0.f, sexp = 0.f, sxl = 0.f, sx = 0.f, slg = 0.f;

    for (int base = 0; base < DD; base += 4096) {
        float loc[8], xs[8]; float run = 0.f;
        int i0 = base + t * 8;
        #pragma unroll
        for (int v = 0; v < 8; v++) {
            int i = i0 + v;
            float dv = (i < DD) ? db[i] : 0.f;
            xs[v] = (i < DD) ? xb[i] : 0.f;
            run += dv;
            loc[v] = run;
        }
        float v = run;
        #pragma unroll
        for (int off = 1; off < 32; off <<= 1) {
            float nv = __shfl_up_sync(0xffffffffu, v, off);
            if (lane >= off) v += nv;
        }
        if (lane == 31) wtot[wid] = v;
        __syncthreads();
        if (wid == 0) {
            float w = (lane < 16) ? wtot[lane] : 0.f;
            #pragma unroll
            for (int off = 1; off < 16; off <<= 1) {
                float nv = __shfl_up_sync(0xffffffffu, w, off);
                if (lane >= off) w += nv;
            }
            if (lane < 16) woff[lane] = w;
        }
        __syncthreads();
        float basf = carry + (wid > 0 ? woff[wid - 1] : 0.f) + (v - run);
        #pragma unroll
        for (int u = 0; u < 8; u++) {
            int i = i0 + u;
            if (i < DD) {
                float logit = basf + loc[u];
                sexp += expf(logit);
                float xv = xs[u];
                sxl = fmaf(xv, logit, sxl);
                sx += xv;
                int xi = (int)xv;
                slg += (xi >= 0 && xi < 32 && (float)xi == xv) ? s_lg[xi]
                                                               : lgammaf(xv + 1.f);
            }
        }
        carry += woff[15];
        __syncthreads();
    }
    float vals4[4] = {sexp, sxl, sx, slg};
    #pragma unroll
    for (int q = 0; q < 4; q++) {
        float s = vals4[q];
        #pragma unroll
        for (int off = 16; off; off >>= 1) s += __shfl_down_sync(0xffffffffu, s, off);
        if (lane == 0) redf[wid] = s;
        __syncthreads();
        if (t == 0) { double a = 0.0; for (int i = 0; i < 16; i++) a += (double)redf[i]; s_acc[q] = a; }
        __syncthreads();
    }
    if (t == 0) {
        double tsexp = s_acc[0], tsxl = s_acc[1], tsx = s_acc[2], tslg = s_acc[3];
        d_mult[b] = lgamma(tsx + 1.0) - tslg + tsxl - tsx * log(tsexp);
    }
}

// ---------------- u = (g - z@WtW)*sD, quad pieces ----------------
__global__ void k_uquad(const float* __restrict__ vlv) {
    int b = blockIdx.x, k = threadIdx.x;
    __shared__ float zs[128];
    __shared__ float rd[128];
    zs[k] = d_z[b * HID + k];
    __syncthreads();
    float wv = 0.f;
    #pragma unroll 8
    for (int k2 = 0; k2 < 128; k2++) wv = fmaf(zs[k2], d_WtW[k2 * HID + k], wv);
    float g = d_g[b * HID + k];
    float sd = expf(0.5f * vlv[k]);
    d_u[b * HID + k] = (g - wv) * sd;
    float z = zs[k];

    rd[k] = z * g; __syncthreads();
    for (int off = 64; off; off >>= 1) { if (k < off) rd[k] += rd[k + off]; __syncthreads(); }
    if (k == 0) d_zg[b] = rd[0];
    __syncthreads();
    rd[k] = z * wv; __syncthreads();
    for (int off = 64; off; off >>= 1) { if (k < off) rd[k] += rd[k + off]; __syncthreads(); }
    if (k == 0) d_zWz[b] = rd[0];
    __syncthreads();
    rd[k] = z * z; __syncthreads();
    for (int off = 64; off; off >>= 1) { if (k < off) rd[k] += rd[k + off]; __syncthreads(); }
    if (k == 0) d_z2[b] = rd[0];
}

// ---------------- final: panel Cholesky + solve + loss ----------------
__global__ __launch_bounds__(512) void k_final(const float* __restrict__ vlv,
                                               const float* __restrict__ lss_ptr,
                                               float* __restrict__ out) {
    extern __shared__ float smf[];
    float* Mm = smf;
    float* R  = smf + 128 * 129;
    __shared__ __align__(16) float Lp[120 * 8];
    __shared__ float sinv[8];
    __shared__ float sD[128];
    __shared__ double s_ld;
    __shared__ double red[512];
    int t = threadIdx.x, lane = t & 31;
    float lss = *lss_ptr;
    float var = expf(lss);
    float ivar = 1.f / var;
    if (t < 128) sD[t] = expf(0.5f * vlv[t]);
    __syncthreads();
    for (int idx = t; idx < 128 * 128; idx += 512) {
        int i = idx >> 7, j = idx & 127;
        float m = sD[i] * d_WtW[idx] * sD[j] * ivar;
        if (i == j) m += 1.f;
        Mm[i * 129 + j] = m;
    }
    for (int idx = t; idx < 128 * 128; idx += 512) {
        int b = idx >> 7, i = idx & 127;
        R[i * 129 + b] = d_u[idx];
    }
    __syncthreads();

    float qacc = 0.f;
    double ldacc = 0.0;

    for (int p = 0; p < 16; p++) {
        int k0 = 8 * p;
        if (t < 32) {
            int r = lane & 7;
            float v[8];
            #pragma unroll
            for (int c = 0; c < 8; c++) v[c] = Mm[(k0 + r) * 129 + k0 + c];
            #pragma unroll
            for (int kk = 0; kk < 8; kk++) {
                float dkk = __shfl_sync(0xffffffffu, v[kk], kk);
                float d = sqrtf(dkk);
                float inv = 1.f / d;
                if (lane == kk) { v[kk] = d; ldacc += 2.0 * log((double)d); }
                if (r > kk && lane != kk) v[kk] *= inv;
                #pragma unroll
                for (int c = kk + 1; c < 8; c++) {
                    float Lck = __shfl_sync(0xffffffffu, v[kk], c);
                    if (r > kk) v[c] -= v[kk] * Lck;
                }
            }
            if (lane < 8) {
                #pragma unroll
                for (int c = 0; c < 8; c++) Mm[(k0 + r) * 129 + k0 + c] = v[c];
                sinv[r] = 1.f / v[r];
            }
        }
        __syncthreads();

        int nrem = 120 - k0;
        if (t < nrem) {
            int i = k0 + 8 + t;
            float a[8];
            #pragma unroll
            for (int c = 0; c < 8; c++) a[c] = Mm[i * 129 + k0 + c];
            #pragma unroll
            for (int c = 0; c < 8; c++) {
                float s = a[c];
                #pragma unroll
                for (int q = 0; q < 8; q++) if (q < c) s -= a[q] * Mm[(k0 + c) * 129 + k0 + q];
                a[c] = s * sinv[c];
            }
            #pragma unroll
            for (int c = 0; c < 8; c++) { Mm[i * 129 + k0 + c] = a[c]; Lp[t * 8 + c] = a[c]; }
        } else if (t >= 256 && t < 384) {
            int b = t - 256;
            float y[8];
            #pragma unroll
            for (int c = 0; c < 8; c++) y[c] = R[(k0 + c) * 129 + b];
            #pragma unroll
            for (int c = 0; c < 8; c++) {
                float s = y[c];
                #pragma unroll
                for (int q = 0; q < 8; q++) if (q < c) s -= y[q] * Mm[(k0 + c) * 129 + k0 + q];
                y[c] = s * sinv[c];
                qacc = fmaf(y[c], y[c], qacc);
            }
            #pragma unroll
            for (int c = 0; c < 8; c++) R[(k0 + c) * 129 + b] = y[c];
        }
        __syncthreads();

        int base = k0 + 8, n = 128 - base;
        if (n > 0) {
            int io = t & 127, jg = t >> 7;
            if (io < n) {
                int i = base + io;
                float Li[8];
                #pragma unroll
                for (int q = 0; q < 8; q++) Li[q] = Lp[io * 8 + q];
                for (int jo = jg; jo < n; jo += 4) {
                    int j = base + jo;
                    const float4* lp4 = (const float4*)&Lp[jo * 8];
                    float4 L0 = lp4[0], L1 = lp4[1];
                    float s = Mm[i * 129 + j];
                    s -= Li[0] * L0.x + Li[1] * L0.y + Li[2] * L0.z + Li[3] * L0.w
                       + Li[4] * L1.x + Li[5] * L1.y + Li[6] * L1.z + Li[7] * L1.w;
                    Mm[i * 129 + j] = s;
                }
            }
            {
                int b = t & 127, ig = t >> 7;
                float y[8];
                #pragma unroll
                for (int q = 0; q < 8; q++) y[q] = R[(k0 + q) * 129 + b];
                for (int io2 = ig; io2 < n; io2 += 4) {
                    int i = base + io2;
                    const float4* lp4 = (const float4*)&Lp[io2 * 8];
                    float4 L0 = lp4[0], L1 = lp4[1];
                    float s = R[i * 129 + b];
                    s -= y[0] * L0.x + y[1] * L0.y + y[2] * L0.z + y[3] * L0.w
                       + y[4] * L1.x + y[5] * L1.y + y[6] * L1.z + y[7] * L1.w;
                    R[i * 129 + b] = s;
                }
            }
        }
        __syncthreads();
    }

    if (t < 32) {
        #pragma unroll
        for (int off = 16; off; off >>= 1) ldacc += __shfl_down_sync(0xffffffffu, ldacc, off);
        if (lane == 0) s_ld = ldacc;
    }
    __syncthreads();

    double acc = 0.0;
    if (t >= 256 && t < 384) {
        int b = t - 256;
        float quad = (d_eta2[b] - 2.f * d_zg[b] + d_zWz[b]) * ivar - qacc * ivar * ivar;
        double logdet = (double)DM1 * (double)lss + s_ld;
        double ll = -0.5 * ((double)DM1 * LOG2PI + logdet + (double)quad);
        acc = ll + d_mult[b] - 0.5 * (double)d_z2[b] / 128.0;
    }
    red[t] = acc;
    __syncthreads();
    for (int off = 256; off; off >>= 1) { if (t < off) red[t] += red[t + off]; __syncthreads(); }
    if (t == 0) {
        double total = red[0] / 128.0 - 0.5 * LOG2PI;
        out[0] = (float)(-total);
    }
}

// ---------------- launcher: stream 0 ONLY forks/joins; all work on private streams ----------------
static cudaStream_t s1, s2, s3;
static cudaEvent_t ev_root, ev_meta, ev_ms, ev_encb, ev_dect, ev_g, ev_w, ev_mult, ev_done;
static bool g_init = false;

extern "C" void kernel_launch(void* const* d_in, const int* in_sizes, int n_in,
                              void* d_out, int out_size) {
    const float* x     = (const float*)d_in[0];
    const int*   rows  = (const int*)  d_in[1];
    const int*   cols  = (const int*)  d_in[2];
    const float* vals  = (const float*)d_in[3];
    const float* enc_w = (const float*)d_in[4];
    const float* dec_w = (const float*)d_in[5];
    const float* vlv   = (const float*)d_in[6];
    const float* lss   = (const float*)d_in[7];
    const float* eta   = (const float*)d_in[8];
    int nnz = in_sizes[1];
    float* out = (float*)d_out;

    if (!g_init) {
        cudaStreamCreateWithFlags(&s1, cudaStreamNonBlocking);
        cudaStreamCreateWithFlags(&s2, cudaStreamNonBlocking);
        cudaStreamCreateWithFlags(&s3, cudaStreamNonBlocking);
        cudaEventCreateWithFlags(&ev_root, cudaEventDisableTiming);
        cudaEventCreateWithFlags(&ev_meta, cudaEventDisableTiming);
        cudaEventCreateWithFlags(&ev_ms,   cudaEventDisableTiming);
        cudaEventCreateWithFlags(&ev_encb, cudaEventDisableTiming);
        cudaEventCreateWithFlags(&ev_dect, cudaEventDisableTiming);
        cudaEventCreateWithFlags(&ev_g,    cudaEventDisableTiming);
        cudaEventCreateWithFlags(&ev_w,    cudaEventDisableTiming);
        cudaEventCreateWithFlags(&ev_mult, cudaEventDisableTiming);
        cudaEventCreateWithFlags(&ev_done, cudaEventDisableTiming);
        cudaFuncSetAttribute(k_final, cudaFuncAttributeMaxDynamicSharedMemorySize,
                             2 * 128 * 129 * (int)sizeof(float));
        cudaFuncSetAttribute(k_scan_hx, cudaFuncAttributeMaxDynamicSharedMemorySize,
                             (DD + 1) * (int)sizeof(float));
        g_init = true;
    }

    void *p_dlt, *p_z, *p_g, *p_w, *p_e2;
    cudaGetSymbolAddress(&p_dlt, d_dlt);
    cudaGetSymbolAddress(&p_z, d_z);
    cudaGetSymbolAddress(&p_g, d_g);
    cudaGetSymbolAddress(&p_w, d_WtW);
    cudaGetSymbolAddress(&p_e2, d_eta2);

    // fork from capture-origin stream: NO kernels on stream 0
    cudaEventRecord(ev_root, 0);
    cudaStreamWaitEvent(s1, ev_root, 0);
    cudaStreamWaitEvent(s2, ev_root, 0);
    cudaStreamWaitEvent(s3, ev_root, 0);

    // s1: meta -> scan_hx -> (encb) gemm_z -> (g,w) uquad -> (mult) final
    k_meta<<<(DM1 + 255) / 256, 256, 0, s1>>>(rows, cols, vals, nnz);
    cudaEventRecord(ev_meta, s1);
    k_scan_hx<<<BB, 512, (DD + 1) * sizeof(float), s1>>>(x);

    // s3: memsets -> cvt_enc -> trans_dec -> gemm_w
    cudaMemsetAsync(p_dlt, 0, (size_t)BB * (DD + 1) * sizeof(float), s3);
    cudaMemsetAsync(p_z, 0, BB * HID * sizeof(float), s3);
    cudaMemsetAsync(p_g, 0, BB * HID * sizeof(float), s3);
    cudaMemsetAsync(p_w, 0, HID * HID * sizeof(float), s3);
    cudaMemsetAsync(p_e2, 0, BB * sizeof(float), s3);
    cudaEventRecord(ev_ms, s3);
    {
        dim3 gcv((ST / 8 + 255) / 256, HID);
        k_cvt<<<gcv, 256, 0, s3>>>(enc_w, d_encb);
    }
    cudaEventRecord(ev_encb, s3);
    k_trans_dec<<<ST / 64, 256, 0, s3>>>(dec_w);
    cudaEventRecord(ev_dect, s3);
    k_gemm_w<<<NBLK2, 256, 0, s3>>>();
    cudaEventRecord(ev_w, s3);

    // s2: (meta, memsets) -> cvt_eta -> (dect) gemm_g -> mult
    cudaStreamWaitEvent(s2, ev_meta, 0);
    cudaStreamWaitEvent(s2, ev_ms, 0);
    {
        dim3 gce((ST / 8 + 255) / 256, BB);
        k_cvt_eta<<<gce, 256, 0, s2>>>(eta);
    }
    cudaStreamWaitEvent(s2, ev_dect, 0);
    k_gemm_g<<<NBLK2, 256, 0, s2>>>();
    cudaEventRecord(ev_g, s2);
    k_mult<<<BB, 512, 0, s2>>>(x);
    cudaEventRecord(ev_mult, s2);

    // s1 tail
    cudaStreamWaitEvent(s1, ev_encb, 0);
    k_gemm_z<<<NBLK2, 256, 0, s1>>>();
    cudaStreamWaitEvent(s1, ev_g, 0);
    cudaStreamWaitEvent(s1, ev_w, 0);
    k_uquad<<<BB, 128, 0, s1>>>(vlv);
    cudaStreamWaitEvent(s1, ev_mult, 0);
    k_final<<<1, 512, 2 * 128 * 129 * sizeof(float), s1>>>(vlv, lss, out);

    // join back to capture-origin stream
    cudaEventRecord(ev_done, s1);
    cudaStreamWaitEvent(0, ev_done, 0);
}

// round 12
// speedup vs baseline: 1.0665x; 1.0072x over previous
#include <cuda_runtime.h>
#include <cuda_bf16.h>
#include <math.h>

#define BB   128
#define DD   20000
#define DM1  19999
#define HID  128
#define ST   20224     // padded bf16 row stride = 79*256
#define JC2  256
#define NBLK2 79
#define LDA  72        // bf16 smem row stride (144B)
#define TILEB (128 * LDA * 2)   // bytes per operand tile (18432)
#define LOG2PI 1.8378770664093453

// ---------------- device scratch ----------------
__device__ float  d_dlt[(size_t)BB * (DD + 1)];
__device__ __nv_bfloat16 d_hxb[(size_t)BB * ST];
__device__ __nv_bfloat16 d_encb[(size_t)HID * ST];
__device__ __nv_bfloat16 d_etab[(size_t)BB * ST];
__device__ __nv_bfloat16 d_dect[(size_t)HID * ST];
__device__ float  d_z[BB * HID];
__device__ float  d_g[BB * HID];
__device__ float  d_WtW[HID * HID];
__device__ float  d_u[BB * HID];
__device__ int    d_lo[DM1], d_mid[DM1], d_hi[DM1];
__device__ float  d_av[DM1], d_bv[DM1];
__device__ double d_mult[BB];
__device__ float  d_eta2[BB];
__device__ float  d_zg[BB], d_zWz[BB], d_z2[BB];

// ---------------- meta ----------------
__device__ __forceinline__ int lower_bound_i(const int* a, int n, int key) {
    int lo = 0, hi = n;
    while (lo < hi) { int m = (lo + hi) >> 1; if (a[m] < key) lo = m + 1; else hi = m; }
    return lo;
}

__global__ void k_meta(const int* __restrict__ rows, const int* __restrict__ cols,
                       const float* __restrict__ vals, int nnz) {
    int r = blockIdx.x * blockDim.x + threadIdx.x;
    if (r >= DM1) return;
    int s = lower_bound_i(rows, nnz, r);
    int e = lower_bound_i(rows, nnz, r + 1);
    d_lo[r] = cols[s];
    d_hi[r] = cols[e - 1] + 1;
    d_av[r] = vals[s];
    d_bv[r] = vals[e - 1];
    int a = s, b = e;
    while (a < b) { int m = (a + b) >> 1; if (vals[m] < 0.f) b = m; else a = m + 1; }
    d_mid[r] = cols[a];
}

// ---------------- scan log(x+1) in smem, emit bf16 hx directly ----------------
__global__ __launch_bounds__(512) void k_scan_hx(const float* __restrict__ x) {
    int b = blockIdx.x, t = threadIdx.x, lane = t & 31, wid = t >> 5;
    extern __shared__ float P[];             // DD+1 floats
    __shared__ double wtot[16], woff[16];
    __shared__ double s_lx[32];
    if (t < 32) s_lx[t] = log((double)t + 1.0);
    __syncthreads();
    const float* xb = x + (size_t)b * DD;
    double carry = 0.0;
    if (t == 0) P[0] = 0.f;

    for (int base = 0; base < DD; base += 4096) {
        double loc[8]; double run = 0.0;
        int i0 = base + t * 8;
        #pragma unroll
        for (int v = 0; v < 8; v++) {
            int i = i0 + v;
            if (i < DD) {
                float xv = xb[i];
                int xi = (int)xv;
                double lv = (xi >= 0 && xi < 32 && (float)xi == xv)
                          ? s_lx[xi] : (double)logf(xv + 1.f);
                run += lv;
            }
            loc[v] = run;
        }
        double v = run;
        #pragma unroll
        for (int off = 1; off < 32; off <<= 1) {
            double nv = __shfl_up_sync(0xffffffffu, v, off);
            if (lane >= off) v += nv;
        }
        if (lane == 31) wtot[wid] = v;
        __syncthreads();
        if (wid == 0) {
            double w = (lane < 16) ? wtot[lane] : 0.0;
            #pragma unroll
            for (int off = 1; off < 16; off <<= 1) {
                double nv = __shfl_up_sync(0xffffffffu, w, off);
                if (lane >= off) w += nv;
            }
            if (lane < 16) woff[lane] = w;
        }
        __syncthreads();
        double basd = carry + (wid > 0 ? woff[wid - 1] : 0.0) + (v - run);
        #pragma unroll
        for (int u = 0; u < 8; u++) {
            int i = i0 + u;
            if (i < DD) P[i + 1] = (float)(basd + loc[u]);
        }
        carry += woff[15];
        __syncthreads();
    }

    __nv_bfloat16* hb = d_hxb + (size_t)b * ST;
    for (int j = t; j < ST; j += 512) {
        float hv = 0.f;
        if (j < DM1) {
            float pl = P[d_lo[j]], pm = P[d_mid[j]], ph = P[d_hi[j]];
            hv = d_av[j] * (pm - pl) + d_bv[j] * (ph - pm);
        }
        hb[j] = __float2bfloat16(hv);
    }
}

// ---------------- eta -> bf16 padded + global scatter + eta^2 ----------------
__global__ __launch_bounds__(256) void k_cvt_eta(const float* __restrict__ eta) {
    int b = blockIdx.y;
    int j0 = 8 * (blockIdx.x * 256 + threadIdx.x);
    float* dp = d_dlt + (size_t)b * (DD + 1);
    const float* eb = eta + (size_t)b * DM1;
    float e[8];
    float s = 0.f;
    #pragma unroll
    for (int v = 0; v < 8; v++) {
        int j = j0 + v;
        float ev = (j < DM1) ? eb[j] : 0.f;
        e[v] = ev;
        s = fmaf(ev, ev, s);
        if (j < DM1) {
            float a = d_av[j], bb = d_bv[j];
            atomicAdd(dp + d_lo[j],  a * ev);
            atomicAdd(dp + d_mid[j], (bb - a) * ev);
            atomicAdd(dp + d_hi[j], -bb * ev);
        }
    }
    if (j0 < ST) {
        unsigned pk[4];
        #pragma unroll
        for (int v = 0; v < 4; v++) {
            __nv_bfloat162 p = __floats2bfloat162_rn(e[2 * v], e[2 * v + 1]);
            pk[v] = *(unsigned*)&p;
        }
        *(uint4*)&d_etab[(size_t)b * ST + j0] = *(uint4*)pk;
    }
    #pragma unroll
    for (int off = 16; off; off >>= 1) s += __shfl_down_sync(0xffffffffu, s, off);
    if ((threadIdx.x & 31) == 0) atomicAdd(&d_eta2[b], s);
}

// ---------------- enc fp32 -> padded bf16 ----------------
__global__ __launch_bounds__(256) void k_cvt(const float* __restrict__ src,
                                             __nv_bfloat16* __restrict__ dst) {
    int r = blockIdx.y;
    int j0 = 8 * (blockIdx.x * 256 + threadIdx.x);
    if (j0 >= ST) return;
    const float* sb = src + (size_t)r * DM1;
    unsigned pk[4];
    #pragma unroll
    for (int v = 0; v < 4; v++) {
        int j = j0 + 2 * v;
        float f1 = (j < DM1)     ? sb[j]     : 0.f;
        float f2 = (j + 1 < DM1) ? sb[j + 1] : 0.f;
        __nv_bfloat162 p = __floats2bfloat162_rn(f1, f2);
        pk[v] = *(unsigned*)&p;
    }
    *(uint4*)&dst[(size_t)r * ST + j0] = *(uint4*)pk;
}

// ---------------- dec [j][128] fp32 -> dect [n][ST] bf16 ----------------
__global__ __launch_bounds__(256) void k_trans_dec(const float* __restrict__ dw) {
    __shared__ __nv_bfloat16 tile[64][132];
    int j0 = blockIdx.x * 64;
    int t = threadIdx.x;
    #pragma unroll
    for (int p = 0; p < 16; p++) {
        int idx = t + 256 * p;
        int jj = idx >> 6, c2 = idx & 63;
        int j = j0 + jj;
        float2 v = make_float2(0.f, 0.f);
        if (j < DM1) v = *(const float2*)(dw + (size_t)j * HID + 2 * c2);
        tile[jj][2 * c2]     = __float2bfloat16(v.x);
        tile[jj][2 * c2 + 1] = __float2bfloat16(v.y);
    }
    __syncthreads();
    #pragma unroll
    for (int p = 0; p < 16; p++) {
        int idx = t + 256 * p;
        int n = idx >> 5, jw = idx & 31;
        __nv_bfloat162 pk;
        pk.x = tile[2 * jw][n];
        pk.y = tile[2 * jw + 1][n];
        *(unsigned*)&d_dect[(size_t)n * ST + j0 + 2 * jw] = *(unsigned*)&pk;
    }
}

// ---------------- mma helpers ----------------
__device__ __forceinline__ void mma_bf16(float* c, unsigned a0, unsigned a1, unsigned a2,
                                         unsigned a3, unsigned b0, unsigned b1) {
    asm volatile("mma.sync.aligned.m16n8k16.row.col.f32.bf16.bf16.f32 "
                 "{%0,%1,%2,%3}, {%4,%5,%6,%7}, {%8,%9}, {%0,%1,%2,%3};\n"
                 : "+f"(c[0]), "+f"(c[1]), "+f"(c[2]), "+f"(c[3])
                 : "r"(a0), "r"(a1), "r"(a2), "r"(a3), "r"(b0), "r"(b1));
}

__device__ __forceinline__ void mma_chunk(const __nv_bfloat16* As, const __nv_bfloat16* Bs,
                                          float acc[4][4][4], int lane, int wm, int wn) {
    #pragma unroll
    for (int kk = 0; kk < 4; kk++) {
        int co = kk * 16 + 2 * (lane & 3);
        unsigned a[4][4], b[4][2];
        #pragma unroll
        for (int mt = 0; mt < 4; mt++) {
            int r = wm * 64 + mt * 16 + (lane >> 2);
            a[mt][0] = *(const unsigned*)&As[r * LDA + co];
            a[mt][1] = *(const unsigned*)&As[(r + 8) * LDA + co];
            a[mt][2] = *(const unsigned*)&As[r * LDA + co + 8];
            a[mt][3] = *(const unsigned*)&As[(r + 8) * LDA + co + 8];
        }
        #pragma unroll
        for (int nt = 0; nt < 4; nt++) {
            int n = wn * 32 + nt * 8 + (lane >> 2);
            b[nt][0] = *(const unsigned*)&Bs[n * LDA + co];
            b[nt][1] = *(const unsigned*)&Bs[n * LDA + co + 8];
        }
        #pragma unroll
        for (int mt = 0; mt < 4; mt++)
            #pragma unroll
            for (int nt = 0; nt < 4; nt++)
                mma_bf16(acc[mt][nt], a[mt][0], a[mt][1], a[mt][2], a[mt][3],
                         b[nt][0], b[nt][1]);
    }
}

__device__ __forceinline__ void gemm_epi(float* C, float acc[4][4][4], int lane, int wm, int wn) {
    #pragma unroll
    for (int mt = 0; mt < 4; mt++)
        #pragma unroll
        for (int nt = 0; nt < 4; nt++) {
            int r = wm * 64 + mt * 16 + (lane >> 2);
            int c = wn * 32 + nt * 8 + 2 * (lane & 3);
            atomicAdd(&C[r * HID + c],           acc[mt][nt][0]);
            atomicAdd(&C[r * HID + c + 1],       acc[mt][nt][1]);
            atomicAdd(&C[(r + 8) * HID + c],     acc[mt][nt][2]);
            atomicAdd(&C[(r + 8) * HID + c + 1], acc[mt][nt][3]);
        }
}

#define CP16(smoff, gptr) \
    asm volatile("cp.async.cg.shared.global [%0], [%1], 16;\n" :: "r"(smoff), "l"(gptr))

// ---------------- cp.async 2-stage pipelined GEMM (dual-operand) ----------------
__device__ __forceinline__ void gemm_pipe(const __nv_bfloat16* __restrict__ A,
                                          const __nv_bfloat16* __restrict__ B,
                                          float* __restrict__ C,
                                          __nv_bfloat16* sm) {
    unsigned sb = (unsigned)__cvta_generic_to_shared(sm);
    int j0 = blockIdx.x * JC2;
    int t = threadIdx.x, lane = t & 31, w = t >> 5;
    int wm = w & 1, wn = w >> 1;
    int lr = t >> 3, lc = (t & 7) * 8;
    float acc[4][4][4];
    #pragma unroll
    for (int a = 0; a < 4; a++)
        #pragma unroll
        for (int b = 0; b < 4; b++)
            #pragma unroll
            for (int c = 0; c < 4; c++) acc[a][b][c] = 0.f;

    // preload chunk 0 -> stage 0
    #pragma unroll
    for (int p = 0; p < 4; p++) {
        int row = lr + 32 * p;
        unsigned off = (unsigned)(row * LDA + lc) * 2u;
        CP16(sb + off,         A + (size_t)row * ST + j0 + lc);
        CP16(sb + TILEB + off, B + (size_t)row * ST + j0 + lc);
    }
    asm volatile("cp.async.commit_group;\n");

    #pragma unroll
    for (int ch = 0; ch < 4; ch++) {
        int st = ch & 1;
        if (ch < 3) {
            int nst = (ch + 1) & 1;
            int js = j0 + (ch + 1) * 64;
            unsigned sbase = sb + (unsigned)(nst * 2 * TILEB);
            #pragma unroll
            for (int p = 0; p < 4; p++) {
                int row = lr + 32 * p;
                unsigned off = (unsigned)(row * LDA + lc) * 2u;
                CP16(sbase + off,         A + (size_t)row * ST + js + lc);
                CP16(sbase + TILEB + off, B + (size_t)row * ST + js + lc);
            }
            asm volatile("cp.async.commit_group;\n");
            asm volatile("cp.async.wait_group 1;\n");
        } else {
            asm volatile("cp.async.wait_group 0;\n");
        }
        __syncthreads();
        const __nv_bfloat16* As = sm + st * 2 * 128 * LDA;
        const __nv_bfloat16* Bs = As + 128 * LDA;
        mma_chunk(As, Bs, acc, lane, wm, wn);
        __syncthreads();
    }
    gemm_epi(C, acc, lane, wm, wn);
}

__global__ __launch_bounds__(256, 2) void k_gemm_z() {
    extern __shared__ __nv_bfloat16 smz[];
    gemm_pipe(d_hxb, d_encb, d_z, smz);
}
__global__ __launch_bounds__(256, 2) void k_gemm_g() {
    extern __shared__ __nv_bfloat16 smg[];
    gemm_pipe(d_etab, d_dect, d_g, smg);
}
// WtW: single operand, 2-stage x 1 tile
__global__ __launch_bounds__(256, 2) void k_gemm_w() {
    extern __shared__ __nv_bfloat16 smw[];
    unsigned sb = (unsigned)__cvta_generic_to_shared(smw);
    int j0 = blockIdx.x * JC2;
    int t = threadIdx.x, lane = t & 31, w = t >> 5;
    int wm = w & 1, wn = w >> 1;
    int lr = t >> 3, lc = (t & 7) * 8;
    float acc[4][4][4];
    #pragma unroll
    for (int a = 0; a < 4; a++)
        #pragma unroll
        for (int b = 0; b < 4; b++)
            #pragma unroll
            for (int c = 0; c < 4; c++) acc[a][b][c] = 0.f;

    #pragma unroll
    for (int p = 0; p < 4; p++) {
        int row = lr + 32 * p;
        unsigned off = (unsigned)(row * LDA + lc) * 2u;
        CP16(sb + off, d_dect + (size_t)row * ST + j0 + lc);
    }
    asm volatile("cp.async.commit_group;\n");

    #pragma unroll
    for (int ch = 0; ch < 4; ch++) {
        int st = ch & 1;
        if (ch < 3) {
            int nst = (ch + 1) & 1;
            int js = j0 + (ch + 1) * 64;
            unsigned sbase = sb + (unsigned)(nst * TILEB);
            #pragma unroll
            for (int p = 0; p < 4; p++) {
                int row = lr + 32 * p;
                unsigned off = (unsigned)(row * LDA + lc) * 2u;
                CP16(sbase + off, d_dect + (size_t)row * ST + js + lc);
            }
            asm volatile("cp.async.commit_group;\n");
            asm volatile("cp.async.wait_group 1;\n");
        } else {
            asm volatile("cp.async.wait_group 0;\n");
        }
        __syncthreads();
        const __nv_bfloat16* As = smw + st * 128 * LDA;
        mma_chunk(As, As, acc, lane, wm, wn);
        __syncthreads();
    }
    gemm_epi(d_WtW, acc, lane, wm, wn);
}

// ---------------- logits scan + multinomial (reads global dlt) ----------------
__global__ __launch_bounds__(512) void k_mult(const float* __restrict__ x) {
    int b = blockIdx.x, t = threadIdx.x, lane = t & 31, wid = t >> 5;
    const float* xb = x + (size_t)b * DD;
    const float* db = d_dlt + (size_t)b * (DD + 1);
    __shared__ float wtot[16], woff[16], redf[16];
    __shared__ float s_lg[32];
    __shared__ double s_acc[4];
    if (t < 32) s_lg[t] = (float)lgamma((double)t + 1.0);
    __syncthreads();
    float carry = 0.f, sexp = 0.f, sxl = 0.f, sx = 0.f, slg = 0.f;

    for (int base = 0; base < DD; base += 4096) {
        float loc[8], xs[8]; float run = 0.f;
        int i0 = base + t * 8;
        #pragma unroll
        for (int v = 0; v < 8; v++) {
            int i = i0 + v;
            float dv = (i < DD) ? db[i] : 0.f;
            xs[v] = (i < DD) ? xb[i] : 0.f;
            run += dv;
            loc[v] = run;
        }
        float v = run;
        #pragma unroll
        for (int off = 1; off < 32; off <<= 1) {
            float nv = __shfl_up_sync(0xffffffffu, v, off);
            if (lane >= off) v += nv;
        }
        if (lane == 31) wtot[wid] = v;
        __syncthreads();
        if (wid == 0) {
            float w = (lane < 16) ? wtot[lane] : 0.f;
            #pragma unroll
            for (int off = 1; off < 16; off <<= 1) {
                float nv = __shfl_up_sync(0xffffffffu, w, off);
                if (lane >= off) w += nv;
            }
            if (lane < 16) woff[lane] = w;
        }
        __syncthreads();
        float basf = carry + (wid > 0 ? woff[wid - 1] : 0.f) + (v - run);
        #pragma unroll
        for (int u = 0; u < 8; u++) {
            int i = i0 + u;
            if (i < DD) {
                float logit = basf + loc[u];
                sexp += expf(logit);
                float xv = xs[u];
                sxl = fmaf(xv, logit, sxl);
                sx += xv;
                int xi = (int)xv;
                slg += (xi >= 0 && xi < 32 && (float)xi == xv) ? s_lg[xi]
                                                               : lgammaf(xv + 1.f);
            }
        }
        carry += woff[15];
        __syncthreads();
    }
    float vals4[4] = {sexp, sxl, sx, slg};
    #pragma unroll
    for (int q = 0; q < 4; q++) {
        float s = vals4[q];
        #pragma unroll
        for (int off = 16; off; off >>= 1) s += __shfl_down_sync(0xffffffffu, s, off);
        if (lane == 0) redf[wid] = s;
        __syncthreads();
        if (t == 0) { double a = 0.0; for (int i = 0; i < 16; i++) a += (double)redf[i]; s_acc[q] = a; }
        __syncthreads();
    }
    if (t == 0) {
        double tsexp = s_acc[0], tsxl = s_acc[1], tsx = s_acc[2], tslg = s_acc[3];
        d_mult[b] = lgamma(tsx + 1.0) - tslg + tsxl - tsx * log(tsexp);
    }
}

// ---------------- u = (g - z@WtW)*sD, quad pieces ----------------
__global__ void k_uquad(const float* __restrict__ vlv) {
    int b = blockIdx.x, k = threadIdx.x;
    __shared__ float zs[128];
    __shared__ float rd[128];
    zs[k] = d_z[b * HID + k];
    __syncthreads();
    float wv = 0.f;
    #pragma unroll 8
    for (int k2 = 0; k2 < 128; k2++) wv = fmaf(zs[k2], d_WtW[k2 * HID + k], wv);
    float g = d_g[b * HID + k];
    float sd = expf(0.5f * vlv[k]);
    d_u[b * HID + k] = (g - wv) * sd;
    float z = zs[k];

    rd[k] = z * g; __syncthreads();
    for (int off = 64; off; off >>= 1) { if (k < off) rd[k] += rd[k + off]; __syncthreads(); }
    if (k == 0) d_zg[b] = rd[0];
    __syncthreads();
    rd[k] = z * wv; __syncthreads();
    for (int off = 64; off; off >>= 1) { if (k < off) rd[k] += rd[k + off]; __syncthreads(); }
    if (k == 0) d_zWz[b] = rd[0];
    __syncthreads();
    rd[k] = z * z; __syncthreads();
    for (int off = 64; off; off >>= 1) { if (k < off) rd[k] += rd[k + off]; __syncthreads(); }
    if (k == 0) d_z2[b] = rd[0];
}

// ---------------- final: panel Cholesky + solve + loss ----------------
__global__ __launch_bounds__(512) void k_final(const float* __restrict__ vlv,
                                               const float* __restrict__ lss_ptr,
                                               float* __restrict__ out) {
    extern __shared__ float smf[];
    float* Mm = smf;
    float* R  = smf + 128 * 129;
    __shared__ __align__(16) float Lp[120 * 8];
    __shared__ float sinv[8];
    __shared__ float sD[128];
    __shared__ double s_ld;
    __shared__ double red[512];
    int t = threadIdx.x, lane = t & 31;
    float lss = *lss_ptr;
    float var = expf(lss);
    float ivar = 1.f / var;
    if (t < 128) sD[t] = expf(0.5f * vlv[t]);
    __syncthreads();
    for (int idx = t; idx < 128 * 128; idx += 512) {
        int i = idx >> 7, j = idx & 127;
        float m = sD[i] * d_WtW[idx] * sD[j] * ivar;
        if (i == j) m += 1.f;
        Mm[i * 129 + j] = m;
    }
    for (int idx = t; idx < 128 * 128; idx += 512) {
        int b = idx >> 7, i = idx & 127;
        R[i * 129 + b] = d_u[idx];
    }
    __syncthreads();

    float qacc = 0.f;
    double ldacc = 0.0;

    for (int p = 0; p < 16; p++) {
        int k0 = 8 * p;
        if (t < 32) {
            int r = lane & 7;
            float v[8];
            #pragma unroll
            for (int c = 0; c < 8; c++) v[c] = Mm[(k0 + r) * 129 + k0 + c];
            #pragma unroll
            for (int kk = 0; kk < 8; kk++) {
                float dkk = __shfl_sync(0xffffffffu, v[kk], kk);
                float d = sqrtf(dkk);
                float inv = 1.f / d;
                if (lane == kk) { v[kk] = d; ldacc += 2.0 * log((double)d); }
                if (r > kk && lane != kk) v[kk] *= inv;
                #pragma unroll
                for (int c = kk + 1; c < 8; c++) {
                    float Lck = __shfl_sync(0xffffffffu, v[kk], c);
                    if (r > kk) v[c] -= v[kk] * Lck;
                }
            }
            if (lane < 8) {
                #pragma unroll
                for (int c = 0; c < 8; c++) Mm[(k0 + r) * 129 + k0 + c] = v[c];
                sinv[r] = 1.f / v[r];
            }
        }
        __syncthreads();

        int nrem = 120 - k0;
        if (t < nrem) {
            int i = k0 + 8 + t;
            float a[8];
            #pragma unroll
            for (int c = 0; c < 8; c++) a[c] = Mm[i * 129 + k0 + c];
            #pragma unroll
            for (int c = 0; c < 8; c++) {
                float s = a[c];
                #pragma unroll
                for (int q = 0; q < 8; q++) if (q < c) s -= a[q] * Mm[(k0 + c) * 129 + k0 + q];
                a[c] = s * sinv[c];
            }
            #pragma unroll
            for (int c = 0; c < 8; c++) { Mm[i * 129 + k0 + c] = a[c]; Lp[t * 8 + c] = a[c]; }
        } else if (t >= 256 && t < 384) {
            int b = t - 256;
            float y[8];
            #pragma unroll
            for (int c = 0; c < 8; c++) y[c] = R[(k0 + c) * 129 + b];
            #pragma unroll
            for (int c = 0; c < 8; c++) {
                float s = y[c];
                #pragma unroll
                for (int q = 0; q < 8; q++) if (q < c) s -= y[q] * Mm[(k0 + c) * 129 + k0 + q];
                y[c] = s * sinv[c];
                qacc = fmaf(y[c], y[c], qacc);
            }
            #pragma unroll
            for (int c = 0; c < 8; c++) R[(k0 + c) * 129 + b] = y[c];
        }
        __syncthreads();

        int base = k0 + 8, n = 128 - base;
        if (n > 0) {
            int io = t & 127, jg = t >> 7;
            if (io < n) {
                int i = base + io;
                float Li[8];
                #pragma unroll
                for (int q = 0; q < 8; q++) Li[q] = Lp[io * 8 + q];
                for (int jo = jg; jo < n; jo += 4) {
                    int j = base + jo;
                    const float4* lp4 = (const float4*)&Lp[jo * 8];
                    float4 L0 = lp4[0], L1 = lp4[1];
                    float s = Mm[i * 129 + j];
                    s -= Li[0] * L0.x + Li[1] * L0.y + Li[2] * L0.z + Li[3] * L0.w
                       + Li[4] * L1.x + Li[5] * L1.y + Li[6] * L1.z + Li[7] * L1.w;
                    Mm[i * 129 + j] = s;
                }
            }
            {
                int b = t & 127, ig = t >> 7;
                float y[8];
                #pragma unroll
                for (int q = 0; q < 8; q++) y[q] = R[(k0 + q) * 129 + b];
                for (int io2 = ig; io2 < n; io2 += 4) {
                    int i = base + io2;
                    const float4* lp4 = (const float4*)&Lp[io2 * 8];
                    float4 L0 = lp4[0], L1 = lp4[1];
                    float s = R[i * 129 + b];
                    s -= y[0] * L0.x + y[1] * L0.y + y[2] * L0.z + y[3] * L0.w
                       + y[4] * L1.x + y[5] * L1.y + y[6] * L1.z + y[7] * L1.w;
                    R[i * 129 + b] = s;
                }
            }
        }
        __syncthreads();
    }

    if (t < 32) {
        #pragma unroll
        for (int off = 16; off; off >>= 1) ldacc += __shfl_down_sync(0xffffffffu, ldacc, off);
        if (lane == 0) s_ld = ldacc;
    }
    __syncthreads();

    double acc = 0.0;
    if (t >= 256 && t < 384) {
        int b = t - 256;
        float quad = (d_eta2[b] - 2.f * d_zg[b] + d_zWz[b]) * ivar - qacc * ivar * ivar;
        double logdet = (double)DM1 * (double)lss + s_ld;
        double ll = -0.5 * ((double)DM1 * LOG2PI + logdet + (double)quad);
        acc = ll + d_mult[b] - 0.5 * (double)d_z2[b] / 128.0;
    }
    red[t] = acc;
    __syncthreads();
    for (int off = 256; off; off >>= 1) { if (t < off) red[t] += red[t + off]; __syncthreads(); }
    if (t == 0) {
        double total = red[0] / 128.0 - 0.5 * LOG2PI;
        out[0] = (float)(-total);
    }
}

// ---------------- launcher: stream 0 only forks/joins (R10 footprint) ----------------
static cudaStream_t s1, s2, s3;
static cudaEvent_t ev_root, ev_meta, ev_ms, ev_encb, ev_dect, ev_g, ev_w, ev_mult, ev_done;
static bool g_init = false;

extern "C" void kernel_launch(void* const* d_in, const int* in_sizes, int n_in,
                              void* d_out, int out_size) {
    const float* x     = (const float*)d_in[0];
    const int*   rows  = (const int*)  d_in[1];
    const int*   cols  = (const int*)  d_in[2];
    const float* vals  = (const float*)d_in[3];
    const float* enc_w = (const float*)d_in[4];
    const float* dec_w = (const float*)d_in[5];
    const float* vlv   = (const float*)d_in[6];
    const float* lss   = (const float*)d_in[7];
    const float* eta   = (const float*)d_in[8];
    int nnz = in_sizes[1];
    float* out = (float*)d_out;

    if (!g_init) {
        cudaStreamCreateWithFlags(&s1, cudaStreamNonBlocking);
        cudaStreamCreateWithFlags(&s2, cudaStreamNonBlocking);
        cudaStreamCreateWithFlags(&s3, cudaStreamNonBlocking);
        cudaEventCreateWithFlags(&ev_root, cudaEventDisableTiming);
        cudaEventCreateWithFlags(&ev_meta, cudaEventDisableTiming);
        cudaEventCreateWithFlags(&ev_ms,   cudaEventDisableTiming);
        cudaEventCreateWithFlags(&ev_encb, cudaEventDisableTiming);
        cudaEventCreateWithFlags(&ev_dect, cudaEventDisableTiming);
        cudaEventCreateWithFlags(&ev_g,    cudaEventDisableTiming);
        cudaEventCreateWithFlags(&ev_w,    cudaEventDisableTiming);
        cudaEventCreateWithFlags(&ev_mult, cudaEventDisableTiming);
        cudaEventCreateWithFlags(&ev_done, cudaEventDisableTiming);
        cudaFuncSetAttribute(k_final, cudaFuncAttributeMaxDynamicSharedMemorySize,
                             2 * 128 * 129 * (int)sizeof(float));
        cudaFuncSetAttribute(k_scan_hx, cudaFuncAttributeMaxDynamicSharedMemorySize,
                             (DD + 1) * (int)sizeof(float));
        cudaFuncSetAttribute(k_gemm_z, cudaFuncAttributeMaxDynamicSharedMemorySize, 4 * TILEB);
        cudaFuncSetAttribute(k_gemm_g, cudaFuncAttributeMaxDynamicSharedMemorySize, 4 * TILEB);
        cudaFuncSetAttribute(k_gemm_w, cudaFuncAttributeMaxDynamicSharedMemorySize, 2 * TILEB);
        g_init = true;
    }

    void *p_dlt, *p_z, *p_g, *p_w, *p_e2;
    cudaGetSymbolAddress(&p_dlt, d_dlt);
    cudaGetSymbolAddress(&p_z, d_z);
    cudaGetSymbolAddress(&p_g, d_g);
    cudaGetSymbolAddress(&p_w, d_WtW);
    cudaGetSymbolAddress(&p_e2, d_eta2);

    // fork from capture-origin stream
    cudaEventRecord(ev_root, 0);
    cudaStreamWaitEvent(s1, ev_root, 0);
    cudaStreamWaitEvent(s2, ev_root, 0);
    cudaStreamWaitEvent(s3, ev_root, 0);

    // s1: meta -> scan_hx -> (encb) gemm_z -> (g,w) uquad -> (mult) final
    k_meta<<<(DM1 + 255) / 256, 256, 0, s1>>>(rows, cols, vals, nnz);
    cudaEventRecord(ev_meta, s1);
    k_scan_hx<<<BB, 512, (DD + 1) * sizeof(float), s1>>>(x);

    // s3: memsets -> cvt_enc -> trans_dec -> gemm_w
    cudaMemsetAsync(p_dlt, 0, (size_t)BB * (DD + 1) * sizeof(float), s3);
    cudaMemsetAsync(p_z, 0, BB * HID * sizeof(float), s3);
    cudaMemsetAsync(p_g, 0, BB * HID * sizeof(float), s3);
    cudaMemsetAsync(p_w, 0, HID * HID * sizeof(float), s3);
    cudaMemsetAsync(p_e2, 0, BB * sizeof(float), s3);
    cudaEventRecord(ev_ms, s3);
    {
        dim3 gcv((ST / 8 + 255) / 256, HID);
        k_cvt<<<gcv, 256, 0, s3>>>(enc_w, d_encb);
    }
    cudaEventRecord(ev_encb, s3);
    k_trans_dec<<<ST / 64, 256, 0, s3>>>(dec_w);
    cudaEventRecord(ev_dect, s3);
    k_gemm_w<<<NBLK2, 256, 2 * TILEB, s3>>>();
    cudaEventRecord(ev_w, s3);

    // s2: (meta, memsets) -> cvt_eta -> (dect) gemm_g -> mult
    cudaStreamWaitEvent(s2, ev_meta, 0);
    cudaStreamWaitEvent(s2, ev_ms, 0);
    {
        dim3 gce((ST / 8 + 255) / 256, BB);
        k_cvt_eta<<<gce, 256, 0, s2>>>(eta);
    }
    cudaStreamWaitEvent(s2, ev_dect, 0);
    k_gemm_g<<<NBLK2, 256, 4 * TILEB, s2>>>();
    cudaEventRecord(ev_g, s2);
    k_mult<<<BB, 512, 0, s2>>>(x);
    cudaEventRecord(ev_mult, s2);

    // s1 tail
    cudaStreamWaitEvent(s1, ev_encb, 0);
    k_gemm_z<<<NBLK2, 256, 4 * TILEB, s1>>>();
    cudaStreamWaitEvent(s1, ev_g, 0);
    cudaStreamWaitEvent(s1, ev_w, 0);
    k_uquad<<<BB, 128, 0, s1>>>(vlv);
    cudaStreamWaitEvent(s1, ev_mult, 0);
    k_final<<<1, 512, 2 * 128 * 129 * sizeof(float), s1>>>(vlv, lss, out);

    // join back
    cudaEventRecord(ev_done, s1);
    cudaStreamWaitEvent(0, ev_done, 0);
}